// round 1
// baseline (speedup 1.0000x reference)
#include <cuda_runtime.h>
#include <cuda_bf16.h>
#include <math.h>

#define NN 50000
#define EE 600000
#define DD 128
#define GNH 5000
#define GNE 60000
#define NG 10
#define EPS_NORM 1e-5f
#define EPS_RED  1e-6f

// ---------------- scratch (device globals; no allocation allowed) ----------
__device__ float g_Ah[NN * DD];
__device__ float g_Bh[NN * DD];
__device__ float g_Dh[NN * DD];
__device__ float g_Eh[NN * DD];
__device__ float g_num[NN * DD];
__device__ float g_den[NN * DD];
__device__ float g_deg[NN];
// stats: [0..1279] = h (10 graphs x 128 feat), [1280..2559] = e
__device__ float g_sum[2 * NG * DD];
__device__ float g_sq[2 * NG * DD];
__device__ float g_mean[2 * NG * DD];
__device__ float g_rstd[2 * NG * DD];

// ---------------- zero scratch each launch (graph-replay safe) -------------
__global__ void zero_kernel() {
    const int nnd = NN * DD;
    const int total = 2 * nnd + NN + 2 * 2 * NG * DD;
    for (int i = blockIdx.x * blockDim.x + threadIdx.x; i < total;
         i += gridDim.x * blockDim.x) {
        if (i < nnd)                g_num[i] = 0.f;
        else if (i < 2 * nnd)       g_den[i - nnd] = 0.f;
        else if (i < 2 * nnd + NN)  g_deg[i - 2 * nnd] = 0.f;
        else {
            int j = i - 2 * nnd - NN;
            if (j < 2 * NG * DD) g_sum[j] = 0.f;
            else                 g_sq[j - 2 * NG * DD] = 0.f;
        }
    }
}

// ---------------- generic GEMM+bias: out[M,128] = X[M,128]@W + b -----------
// block = 256 threads (8 warps), tile = 64 rows x 128 cols, K=128 full.
// smem: W 128x128 (64KB) + X tile 64x128 (32KB) = 96KB dynamic.
__global__ void gemm_bias(const float* __restrict__ X, const float* __restrict__ W,
                          const float* __restrict__ bias, float* __restrict__ out,
                          int M) {
    extern __shared__ float sm[];
    float* sW = sm;              // 16384 floats
    float* sX = sm + DD * DD;    // 8192 floats

    // load W cooperatively
    {
        const float4* W4 = (const float4*)W;
        float4* sW4 = (float4*)sW;
        for (int i = threadIdx.x; i < DD * 32; i += blockDim.x) sW4[i] = W4[i];
    }
    const int lane = threadIdx.x & 31;
    const int warp = threadIdx.x >> 5;
    const float4 bv = ((const float4*)bias)[lane];

    for (int tile = blockIdx.x * 64; tile < M; tile += gridDim.x * 64) {
        __syncthreads();
        {
            int nrow = min(64, M - tile);
            const float4* X4 = (const float4*)(X + (size_t)tile * DD);
            float4* sX4 = (float4*)sX;
            for (int i = threadIdx.x; i < nrow * 32; i += blockDim.x) sX4[i] = X4[i];
        }
        __syncthreads();

        const int r0 = warp * 8;
        float4 acc[8];
#pragma unroll
        for (int r = 0; r < 8; r++) acc[r] = bv;

#pragma unroll 4
        for (int k = 0; k < DD; k++) {
            float4 wv = ((const float4*)sW)[k * 32 + lane];
#pragma unroll
            for (int r = 0; r < 8; r++) {
                float x = sX[(r0 + r) * DD + k];
                acc[r].x = fmaf(x, wv.x, acc[r].x);
                acc[r].y = fmaf(x, wv.y, acc[r].y);
                acc[r].z = fmaf(x, wv.z, acc[r].z);
                acc[r].w = fmaf(x, wv.w, acc[r].w);
            }
        }
#pragma unroll
        for (int r = 0; r < 8; r++) {
            int row = tile + r0 + r;
            if (row < M) ((float4*)out)[(size_t)row * 32 + lane] = acc[r];
        }
    }
}

// ---------------- fused edge pipeline --------------------------------------
// Ce = e@W2+b2 ; e_new = Ce + Dh[src] + Eh[dst]
// write e_new*snorm_e to out; sig=sigmoid(e_new);
// atomic num[dst]+=sig*Bh[src]; den[dst]+=sig; deg[dst]+=1
__global__ void edge_fused(const float* __restrict__ Ein, const float* __restrict__ W2,
                           const float* __restrict__ b2, const int* __restrict__ src,
                           const int* __restrict__ dst, const float* __restrict__ snorm_e,
                           float* __restrict__ eout) {
    extern __shared__ float sm[];
    float* sW = sm;
    float* sX = sm + DD * DD;
    {
        const float4* W4 = (const float4*)W2;
        float4* sW4 = (float4*)sW;
        for (int i = threadIdx.x; i < DD * 32; i += blockDim.x) sW4[i] = W4[i];
    }
    const int lane = threadIdx.x & 31;
    const int warp = threadIdx.x >> 5;
    const float4 bv = ((const float4*)b2)[lane];
    const float se = snorm_e[0];

    for (int tile = blockIdx.x * 64; tile < EE; tile += gridDim.x * 64) {
        __syncthreads();
        {
            int nrow = min(64, EE - tile);
            const float4* X4 = (const float4*)(Ein + (size_t)tile * DD);
            float4* sX4 = (float4*)sX;
            for (int i = threadIdx.x; i < nrow * 32; i += blockDim.x) sX4[i] = X4[i];
        }
        __syncthreads();

        const int r0 = warp * 8;
        float4 acc[8];
#pragma unroll
        for (int r = 0; r < 8; r++) acc[r] = bv;

#pragma unroll 4
        for (int k = 0; k < DD; k++) {
            float4 wv = ((const float4*)sW)[k * 32 + lane];
#pragma unroll
            for (int r = 0; r < 8; r++) {
                float x = sX[(r0 + r) * DD + k];
                acc[r].x = fmaf(x, wv.x, acc[r].x);
                acc[r].y = fmaf(x, wv.y, acc[r].y);
                acc[r].z = fmaf(x, wv.z, acc[r].z);
                acc[r].w = fmaf(x, wv.w, acc[r].w);
            }
        }

        // epilogue: gather + sigmoid + atomics + store
#pragma unroll
        for (int r = 0; r < 8; r++) {
            int row = tile + r0 + r;
            if (row >= EE) break;
            int s = __ldg(&src[row]);
            int d = __ldg(&dst[row]);
            float4 dh = ((const float4*)g_Dh)[(size_t)s * 32 + lane];
            float4 eh = ((const float4*)g_Eh)[(size_t)d * 32 + lane];
            float4 bh = ((const float4*)g_Bh)[(size_t)s * 32 + lane];
            float ex = acc[r].x + dh.x + eh.x;
            float ey = acc[r].y + dh.y + eh.y;
            float ez = acc[r].z + dh.z + eh.z;
            float ew = acc[r].w + dh.w + eh.w;
            ((float4*)eout)[(size_t)row * 32 + lane] =
                make_float4(ex * se, ey * se, ez * se, ew * se);
            float sx = 1.f / (1.f + expf(-ex));
            float sy = 1.f / (1.f + expf(-ey));
            float sz = 1.f / (1.f + expf(-ez));
            float sw = 1.f / (1.f + expf(-ew));
            int base = d * DD + lane * 4;
            atomicAdd(&g_num[base + 0], sx * bh.x);
            atomicAdd(&g_num[base + 1], sy * bh.y);
            atomicAdd(&g_num[base + 2], sz * bh.z);
            atomicAdd(&g_num[base + 3], sw * bh.w);
            atomicAdd(&g_den[base + 0], sx);
            atomicAdd(&g_den[base + 1], sy);
            atomicAdd(&g_den[base + 2], sz);
            atomicAdd(&g_den[base + 3], sw);
            if (lane == 0) atomicAdd(&g_deg[d], 1.f);
        }
    }
}

// ---------------- node epilogue: h_agg, zero-degree passthrough, *snorm ----
__global__ void node_epi(const float* __restrict__ h, const float* __restrict__ snorm_n,
                         float* __restrict__ outh) {
    const float sn = snorm_n[0];
    const int tot = NN * DD;
    for (int i = blockIdx.x * blockDim.x + threadIdx.x; i < tot;
         i += gridDim.x * blockDim.x) {
        int row = i >> 7;
        float a = g_Ah[i] + g_num[i] / (g_den[i] + EPS_RED);
        float hv = (g_deg[row] > 0.f) ? a : h[i];
        outh[i] = hv * sn;
    }
}

// ---------------- per-graph per-feature sum / sumsq -------------------------
// grid = (chunks, NG); block = 128 (thread = feature)
__global__ void stats_kernel(const float* __restrict__ x, int size, int statOff) {
    int g = blockIdx.y;
    int per = (size + gridDim.x - 1) / gridDim.x;
    int r0 = blockIdx.x * per;
    int r1 = min(size, r0 + per);
    int f = threadIdx.x;
    const float* base = x + (size_t)g * size * DD;
    float s = 0.f, q = 0.f;
    for (int r = r0; r < r1; r++) {
        float v = base[(size_t)r * DD + f];
        s += v;
        q = fmaf(v, v, q);
    }
    if (r0 < r1) {
        atomicAdd(&g_sum[statOff + g * DD + f], s);
        atomicAdd(&g_sq[statOff + g * DD + f], q);
    }
}

__global__ void meanstd_kernel() {
    int i = blockIdx.x * blockDim.x + threadIdx.x;
    if (i >= 2 * NG * DD) return;
    float n = (i < NG * DD) ? (float)GNH : (float)GNE;
    float s = g_sum[i], q = g_sq[i];
    float mean = s / n;
    float var = (q - s * mean) / (n - 1.f);
    var = fmaxf(var, 0.f);
    g_mean[i] = mean;
    g_rstd[i] = 1.f / (sqrtf(var) + EPS_NORM);
}

// ---------------- finalize: graphnorm + affine + relu + residual ------------
// grid = (blocksPerGraph, NG)
__global__ void finalize_kernel(float* __restrict__ io, const float* __restrict__ resid,
                                const float* __restrict__ gamma,
                                const float* __restrict__ beta, int size, int statOff) {
    int g = blockIdx.y;
    size_t base = (size_t)g * size * DD;
    int tot = size * DD;
    for (int i = blockIdx.x * blockDim.x + threadIdx.x; i < tot;
         i += gridDim.x * blockDim.x) {
        int f = i & 127;
        float xv = io[base + i];
        float v = gamma[f] * ((xv - g_mean[statOff + g * DD + f]) *
                              g_rstd[statOff + g * DD + f]) + beta[f];
        io[base + i] = resid[base + i] + fmaxf(v, 0.f);
    }
}

// ---------------- launcher ---------------------------------------------------
extern "C" void kernel_launch(void* const* d_in, const int* in_sizes, int n_in,
                              void* d_out, int out_size) {
    const float* h   = (const float*)d_in[0];
    const float* e   = (const float*)d_in[1];
    const int*   src = (const int*)d_in[2];
    const int*   dst = (const int*)d_in[3];
    const float* snn = (const float*)d_in[4];
    const float* sne = (const float*)d_in[5];
    const float* W   = (const float*)d_in[6];
    const float* b   = (const float*)d_in[7];
    const float* gam_h = (const float*)d_in[8];
    const float* bet_h = (const float*)d_in[9];
    const float* gam_e = (const float*)d_in[10];
    const float* bet_e = (const float*)d_in[11];

    float* out_h = (float*)d_out;
    float* out_e = out_h + (size_t)NN * DD;

    float *pAh, *pBh, *pDh, *pEh;
    cudaGetSymbolAddress((void**)&pAh, g_Ah);
    cudaGetSymbolAddress((void**)&pBh, g_Bh);
    cudaGetSymbolAddress((void**)&pDh, g_Dh);
    cudaGetSymbolAddress((void**)&pEh, g_Eh);

    const int smem = (DD * DD + 64 * DD) * sizeof(float); // 96KB
    cudaFuncSetAttribute((const void*)gemm_bias,
                         cudaFuncAttributeMaxDynamicSharedMemorySize, smem);
    cudaFuncSetAttribute((const void*)edge_fused,
                         cudaFuncAttributeMaxDynamicSharedMemorySize, smem);

    zero_kernel<<<2048, 256>>>();

    const int gridN = (NN + 63) / 64;       // 782 tiles
    gemm_bias<<<gridN, 256, smem>>>(h, W + 0 * DD * DD, b + 0 * DD, pAh, NN);
    gemm_bias<<<gridN, 256, smem>>>(h, W + 1 * DD * DD, b + 1 * DD, pBh, NN);
    gemm_bias<<<gridN, 256, smem>>>(h, W + 3 * DD * DD, b + 3 * DD, pDh, NN);
    gemm_bias<<<gridN, 256, smem>>>(h, W + 4 * DD * DD, b + 4 * DD, pEh, NN);

    edge_fused<<<EE / 64, 256, smem>>>(e, W + 2 * DD * DD, b + 2 * DD,
                                       src, dst, sne, out_e);

    node_epi<<<4096, 256>>>(h, snn, out_h);

    stats_kernel<<<dim3(64, NG), 128>>>(out_h, GNH, 0);
    stats_kernel<<<dim3(256, NG), 128>>>(out_e, GNE, NG * DD);
    meanstd_kernel<<<10, 256>>>();

    finalize_kernel<<<dim3(160, NG), 256>>>(out_h, h, gam_h, bet_h, GNH, 0);
    finalize_kernel<<<dim3(1024, NG), 256>>>(out_e, e, gam_e, bet_e, GNE, NG * DD);
}

// round 3
// speedup vs baseline: 1.2408x; 1.2408x over previous
#include <cuda_runtime.h>
#include <cuda_bf16.h>
#include <math.h>
#include <stdint.h>

#define NN 50000
#define EE 600000
#define DD 128
#define GNH 5000
#define GNE 60000
#define NG 10
#define EPS_NORM 1e-5f
#define EPS_RED  1e-6f

#define MT 64
#define NODE_TILES ((NN + MT - 1) / MT)   // 782
#define EDGE_TILES (EE / MT)              // 9375 (exact)

// smem layout (bytes): A rows 64 x 272B (hi, lo), W rows 128 x 272B (hi, lo)
#define SA_HI 0
#define SA_LO 17408
#define SW_HI 34816
#define SW_LO 69632
#define SMEM_BYTES 104448

// ---------------- scratch (device globals; no allocation allowed) ----------
__device__ float g_Ah[NN * DD];
__device__ float g_Bh[NN * DD];
__device__ float g_Dh[NN * DD];
__device__ float g_Eh[NN * DD];
__device__ float g_num[NN * DD];
__device__ float g_den[NN * DD];
__device__ float g_sum[2 * NG * DD];
__device__ float g_sq[2 * NG * DD];
__device__ float g_mean[2 * NG * DD];
__device__ float g_rstd[2 * NG * DD];
__device__ __nv_bfloat16 g_Wt_hi[5 * DD * DD];   // transposed: [l][n][k]
__device__ __nv_bfloat16 g_Wt_lo[5 * DD * DD];

// ---------------- helpers ----------------------------------------------------
__device__ __forceinline__ uint32_t smem_u32(const void* p) {
    uint32_t a;
    asm("{ .reg .u64 t; cvta.to.shared.u64 t, %1; cvt.u32.u64 %0, t; }" : "=r"(a) : "l"(p));
    return a;
}
__device__ __forceinline__ void ldsm4(uint32_t a[4], uint32_t addr) {
    asm volatile("ldmatrix.sync.aligned.m8n8.x4.shared.b16 {%0,%1,%2,%3}, [%4];"
                 : "=r"(a[0]), "=r"(a[1]), "=r"(a[2]), "=r"(a[3]) : "r"(addr));
}
__device__ __forceinline__ void mma16816(float c[4], const uint32_t a[4],
                                         uint32_t b0, uint32_t b1) {
    asm volatile("mma.sync.aligned.m16n8k16.row.col.f32.bf16.bf16.f32 "
                 "{%0,%1,%2,%3}, {%4,%5,%6,%7}, {%8,%9}, {%0,%1,%2,%3};"
                 : "+f"(c[0]), "+f"(c[1]), "+f"(c[2]), "+f"(c[3])
                 : "r"(a[0]), "r"(a[1]), "r"(a[2]), "r"(a[3]), "r"(b0), "r"(b1));
}
__device__ __forceinline__ void redv4(float* p, float4 v) {
    asm volatile("red.global.add.v4.f32 [%0], {%1,%2,%3,%4};"
                 :: "l"(p), "f"(v.x), "f"(v.y), "f"(v.z), "f"(v.w) : "memory");
}

// ---------------- zero scratch ----------------------------------------------
__global__ void zero_kernel() {
    const int nnd = NN * DD;
    const int total = 2 * nnd + 2 * 2 * NG * DD;
    for (int i = blockIdx.x * blockDim.x + threadIdx.x; i < total;
         i += gridDim.x * blockDim.x) {
        if (i < nnd)           g_num[i] = 0.f;
        else if (i < 2 * nnd)  g_den[i - nnd] = 0.f;
        else {
            int j = i - 2 * nnd;
            if (j < 2 * NG * DD) g_sum[j] = 0.f;
            else                 g_sq[j - 2 * NG * DD] = 0.f;
        }
    }
}

// transpose + split W: Wt[l][n][k] = W[l][k][n]
__global__ void splitW_kernel(const float* __restrict__ W) {
    int i = blockIdx.x * blockDim.x + threadIdx.x;
    if (i >= 5 * DD * DD) return;
    int l = i >> 14, j = i & 16383, n = j >> 7, k = j & 127;
    float v = W[(l << 14) + (k << 7) + n];
    __nv_bfloat16 h = __float2bfloat16_rn(v);
    g_Wt_hi[i] = h;
    g_Wt_lo[i] = __float2bfloat16_rn(v - __bfloat162float(h));
}

// ---------------- tile loader: f32 global -> bf16 hi/lo smem (padded 272B) ---
__device__ __forceinline__ void load_tiles(char* sm, const float* __restrict__ X,
        const __nv_bfloat16* __restrict__ Wh, const __nv_bfloat16* __restrict__ Wl,
        long tile, int M) {
    const int t = threadIdx.x;
    const float2* X2 = (const float2*)X;
    for (int u = t; u < MT * 64; u += 256) {
        int r = u >> 6, kk = u & 63;
        long grow = tile * MT + r;
        float2 v = make_float2(0.f, 0.f);
        if (grow < M) v = X2[grow * 64 + kk];
        __nv_bfloat16 hx = __float2bfloat16_rn(v.x);
        __nv_bfloat16 hy = __float2bfloat16_rn(v.y);
        __nv_bfloat16 lx = __float2bfloat16_rn(v.x - __bfloat162float(hx));
        __nv_bfloat16 ly = __float2bfloat16_rn(v.y - __bfloat162float(hy));
        *(__nv_bfloat162*)(sm + SA_HI + r * 272 + kk * 4) = __nv_bfloat162(hx, hy);
        *(__nv_bfloat162*)(sm + SA_LO + r * 272 + kk * 4) = __nv_bfloat162(lx, ly);
    }
    const uint32_t* WH = (const uint32_t*)Wh;
    const uint32_t* WL = (const uint32_t*)Wl;
    for (int u = t; u < 128 * 64; u += 256) {
        int r = u >> 6, kk = u & 63;
        *(uint32_t*)(sm + SW_HI + r * 272 + kk * 4) = WH[r * 64 + kk];
        *(uint32_t*)(sm + SW_LO + r * 272 + kk * 4) = WL[r * 64 + kk];
    }
    __syncthreads();
}

// ---------------- warp-mma compute: 64x128 tile, warp = 32x32 ----------------
__device__ __forceinline__ void mma_compute(uint32_t smb, float c[2][4][4]) {
    const int lane = threadIdx.x & 31;
    const int w = threadIdx.x >> 5;
    const int m0 = (w & 1) * 32, n0 = (w >> 1) * 32;
#pragma unroll
    for (int m = 0; m < 2; m++)
#pragma unroll
        for (int n = 0; n < 4; n++)
#pragma unroll
            for (int i = 0; i < 4; i++) c[m][n][i] = 0.f;

    const uint32_t aBase = smb + SA_HI + (m0 + (lane & 15)) * 272 + (lane >> 4) * 16;
    const uint32_t bBase = smb + SW_HI +
        (n0 + (lane & 7) + ((lane >> 4) & 1) * 8) * 272 + ((lane >> 3) & 1) * 16;

#pragma unroll
    for (int k = 0; k < 8; k++) {
        uint32_t aH0[4], aH1[4], aL0[4], aL1[4];
        ldsm4(aH0, aBase + k * 32);
        ldsm4(aH1, aBase + 16 * 272 + k * 32);
        ldsm4(aL0, aBase + (SA_LO - SA_HI) + k * 32);
        ldsm4(aL1, aBase + (SA_LO - SA_HI) + 16 * 272 + k * 32);
#pragma unroll
        for (int np = 0; np < 2; np++) {
            uint32_t bH[4], bL[4];
            ldsm4(bH, bBase + np * 16 * 272 + k * 32);
            ldsm4(bL, bBase + (SW_LO - SW_HI) + np * 16 * 272 + k * 32);
#pragma unroll
            for (int nn = 0; nn < 2; nn++) {
                const int nc = np * 2 + nn;
                mma16816(c[0][nc], aH0, bH[nn * 2], bH[nn * 2 + 1]);
                mma16816(c[1][nc], aH1, bH[nn * 2], bH[nn * 2 + 1]);
                mma16816(c[0][nc], aL0, bH[nn * 2], bH[nn * 2 + 1]);
                mma16816(c[1][nc], aL1, bH[nn * 2], bH[nn * 2 + 1]);
                mma16816(c[0][nc], aH0, bL[nn * 2], bL[nn * 2 + 1]);
                mma16816(c[1][nc], aH1, bL[nn * 2], bL[nn * 2 + 1]);
            }
        }
    }
}

// ---------------- node GEMMs: 4 layers via blockIdx.y ------------------------
__global__ void __launch_bounds__(256) node_gemm(const float* __restrict__ h,
                                                 const float* __restrict__ b) {
    extern __shared__ __align__(16) char sm[];
    const int lmap[4] = {0, 1, 3, 4};
    const int l = lmap[blockIdx.y];
    float* outs0 = g_Ah; float* outs1 = g_Bh; float* outs2 = g_Dh; float* outs3 = g_Eh;
    float* out = (blockIdx.y == 0) ? outs0 : (blockIdx.y == 1) ? outs1
               : (blockIdx.y == 2) ? outs2 : outs3;
    const long tile = blockIdx.x;

    load_tiles(sm, h, g_Wt_hi + l * DD * DD, g_Wt_lo + l * DD * DD, tile, NN);
    float c[2][4][4];
    mma_compute(smem_u32(sm), c);

    const float* bias = b + l * DD;
    const int lane = threadIdx.x & 31, w = threadIdx.x >> 5;
    const int m0 = (w & 1) * 32, n0 = (w >> 1) * 32;
    const int tig = lane & 3, gg = lane >> 2;
#pragma unroll
    for (int m = 0; m < 2; m++) {
        long r0 = tile * MT + m0 + m * 16 + gg;
#pragma unroll
        for (int n = 0; n < 4; n++) {
            int col = n0 + n * 8 + tig * 2;
            float2 bv = *(const float2*)(bias + col);
            if (r0 < NN)
                *(float2*)(out + r0 * DD + col) =
                    make_float2(c[m][n][0] + bv.x, c[m][n][1] + bv.y);
            if (r0 + 8 < NN)
                *(float2*)(out + (r0 + 8) * DD + col) =
                    make_float2(c[m][n][2] + bv.x, c[m][n][3] + bv.y);
        }
    }
}

// ---------------- edge GEMM + fused message/agg/stats epilogue ---------------
__global__ void __launch_bounds__(256) edge_gemm(const float* __restrict__ e,
        const float* __restrict__ b2, const int* __restrict__ src,
        const int* __restrict__ dst, const float* __restrict__ snorm_e,
        float* __restrict__ eout) {
    extern __shared__ __align__(16) char sm[];
    const long tile = blockIdx.x;

    load_tiles(sm, e, g_Wt_hi + 2 * DD * DD, g_Wt_lo + 2 * DD * DD, tile, EE);
    float c[2][4][4];
    mma_compute(smem_u32(sm), c);
    __syncthreads();   // sD overlaps A-tile region other warps still read

    float* sD = (float*)sm;   // 64 rows x 132 floats
    const int lane = threadIdx.x & 31, w = threadIdx.x >> 5;
    const int m0 = (w & 1) * 32, n0 = (w >> 1) * 32;
    const int tig = lane & 3, gg = lane >> 2;
#pragma unroll
    for (int m = 0; m < 2; m++) {
        int r = m0 + m * 16 + gg;
#pragma unroll
        for (int n = 0; n < 4; n++) {
            int col = n0 + n * 8 + tig * 2;
            *(float2*)(sD + r * 132 + col) = make_float2(c[m][n][0], c[m][n][1]);
            *(float2*)(sD + (r + 8) * 132 + col) = make_float2(c[m][n][2], c[m][n][3]);
        }
    }
    __syncthreads();

    const float se = snorm_e[0];
    const float4 bb = ((const float4*)b2)[lane];
    int gcur = -1;
    float4 s4 = make_float4(0, 0, 0, 0), q4 = make_float4(0, 0, 0, 0);
#pragma unroll 1
    for (int r = 0; r < 8; r++) {
        const int row = w * 8 + r;
        const long grow = tile * MT + row;
        const int s = __ldg(&src[grow]);
        const int d = __ldg(&dst[grow]);
        float4 dv = *(float4*)(sD + row * 132 + lane * 4);
        float4 dh = ((const float4*)g_Dh)[(size_t)s * 32 + lane];
        float4 eh = ((const float4*)g_Eh)[(size_t)d * 32 + lane];
        float4 bh = ((const float4*)g_Bh)[(size_t)s * 32 + lane];
        float ex = dv.x + bb.x + dh.x + eh.x;
        float ey = dv.y + bb.y + dh.y + eh.y;
        float ez = dv.z + bb.z + dh.z + eh.z;
        float ew = dv.w + bb.w + dh.w + eh.w;
        float4 eo = make_float4(ex * se, ey * se, ez * se, ew * se);
        ((float4*)eout)[(size_t)grow * 32 + lane] = eo;
        float sx = 1.f / (1.f + __expf(-ex));
        float sy = 1.f / (1.f + __expf(-ey));
        float sz = 1.f / (1.f + __expf(-ez));
        float sv = 1.f / (1.f + __expf(-ew));
        redv4(&g_num[d * DD + lane * 4],
              make_float4(sx * bh.x, sy * bh.y, sz * bh.z, sv * bh.w));
        redv4(&g_den[d * DD + lane * 4], make_float4(sx, sy, sz, sv));
        const int gid = (int)(grow / GNE);
        if (gid != gcur) {
            if (gcur >= 0) {
                redv4(&g_sum[NG * DD + gcur * DD + lane * 4], s4);
                redv4(&g_sq[NG * DD + gcur * DD + lane * 4], q4);
            }
            gcur = gid;
            s4 = make_float4(0, 0, 0, 0);
            q4 = make_float4(0, 0, 0, 0);
        }
        s4.x += eo.x; s4.y += eo.y; s4.z += eo.z; s4.w += eo.w;
        q4.x = fmaf(eo.x, eo.x, q4.x); q4.y = fmaf(eo.y, eo.y, q4.y);
        q4.z = fmaf(eo.z, eo.z, q4.z); q4.w = fmaf(eo.w, eo.w, q4.w);
    }
    if (gcur >= 0) {
        redv4(&g_sum[NG * DD + gcur * DD + lane * 4], s4);
        redv4(&g_sq[NG * DD + gcur * DD + lane * 4], q4);
    }
}

// ---------------- node epilogue (den>0 <=> deg>0 since sigmoid>0) -----------
__global__ void node_epi(const float* __restrict__ h, const float* __restrict__ snorm_n,
                         float* __restrict__ outh) {
    const float sn = snorm_n[0];
    const int tot = NN * DD;
    for (int i = blockIdx.x * blockDim.x + threadIdx.x; i < tot;
         i += gridDim.x * blockDim.x) {
        float den = g_den[i];
        float a = g_Ah[i] + g_num[i] / (den + EPS_RED);
        float hv = (den > 0.f) ? a : h[i];
        outh[i] = hv * sn;
    }
}

// ---------------- per-graph per-feature stats for h ---------------------------
__global__ void stats_kernel(const float* __restrict__ x, int size, int statOff) {
    int g = blockIdx.y;
    int per = (size + gridDim.x - 1) / gridDim.x;
    int r0 = blockIdx.x * per;
    int r1 = min(size, r0 + per);
    int f = threadIdx.x;
    const float* base = x + (size_t)g * size * DD;
    float s = 0.f, q = 0.f;
    for (int r = r0; r < r1; r++) {
        float v = base[(size_t)r * DD + f];
        s += v;
        q = fmaf(v, v, q);
    }
    if (r0 < r1) {
        atomicAdd(&g_sum[statOff + g * DD + f], s);
        atomicAdd(&g_sq[statOff + g * DD + f], q);
    }
}

__global__ void meanstd_kernel() {
    int i = blockIdx.x * blockDim.x + threadIdx.x;
    if (i >= 2 * NG * DD) return;
    float n = (i < NG * DD) ? (float)GNH : (float)GNE;
    float s = g_sum[i], q = g_sq[i];
    float mean = s / n;
    float var = (q - s * mean) / (n - 1.f);
    var = fmaxf(var, 0.f);
    g_mean[i] = mean;
    g_rstd[i] = 1.f / (sqrtf(var) + EPS_NORM);
}

// ---------------- finalize: graphnorm + affine + relu + residual -------------
__global__ void finalize_kernel(float* __restrict__ io, const float* __restrict__ resid,
                                const float* __restrict__ gamma,
                                const float* __restrict__ beta, int size, int statOff) {
    int g = blockIdx.y;
    size_t base = (size_t)g * size * DD;
    int tot = size * DD;
    for (int i = blockIdx.x * blockDim.x + threadIdx.x; i < tot;
         i += gridDim.x * blockDim.x) {
        int f = i & 127;
        float xv = io[base + i];
        float v = gamma[f] * ((xv - g_mean[statOff + g * DD + f]) *
                              g_rstd[statOff + g * DD + f]) + beta[f];
        io[base + i] = resid[base + i] + fmaxf(v, 0.f);
    }
}

// ---------------- launcher -----------------------------------------------------
extern "C" void kernel_launch(void* const* d_in, const int* in_sizes, int n_in,
                              void* d_out, int out_size) {
    const float* h   = (const float*)d_in[0];
    const float* e   = (const float*)d_in[1];
    const int*   src = (const int*)d_in[2];
    const int*   dst = (const int*)d_in[3];
    const float* snn = (const float*)d_in[4];
    const float* sne = (const float*)d_in[5];
    const float* W   = (const float*)d_in[6];
    const float* b   = (const float*)d_in[7];
    const float* gam_h = (const float*)d_in[8];
    const float* bet_h = (const float*)d_in[9];
    const float* gam_e = (const float*)d_in[10];
    const float* bet_e = (const float*)d_in[11];

    float* out_h = (float*)d_out;
    float* out_e = out_h + (size_t)NN * DD;

    cudaFuncSetAttribute((const void*)node_gemm,
                         cudaFuncAttributeMaxDynamicSharedMemorySize, SMEM_BYTES);
    cudaFuncSetAttribute((const void*)edge_gemm,
                         cudaFuncAttributeMaxDynamicSharedMemorySize, SMEM_BYTES);

    zero_kernel<<<1024, 256>>>();
    splitW_kernel<<<(5 * DD * DD + 255) / 256, 256>>>(W);

    node_gemm<<<dim3(NODE_TILES, 4), 256, SMEM_BYTES>>>(h, b);
    edge_gemm<<<EDGE_TILES, 256, SMEM_BYTES>>>(e, b + 2 * DD, src, dst, sne, out_e);

    node_epi<<<2048, 256>>>(h, snn, out_h);

    stats_kernel<<<dim3(64, NG), 128>>>(out_h, GNH, 0);
    meanstd_kernel<<<10, 256>>>();

    finalize_kernel<<<dim3(160, NG), 256>>>(out_h, h, gam_h, bet_h, GNH, 0);
    finalize_kernel<<<dim3(1024, NG), 256>>>(out_e, e, gam_e, bet_e, GNE, NG * DD);
}

// round 4
// speedup vs baseline: 1.8850x; 1.5192x over previous
#include <cuda_runtime.h>
#include <cuda_bf16.h>
#include <math.h>
#include <stdint.h>

#define NN 50000
#define EE 600000
#define DD 128
#define GNH 5000
#define GNE 60000
#define NG 10
#define EPS_NORM 1e-5f
#define EPS_RED  1e-6f

#define MT 64
#define NODE_TILES ((NN + MT - 1) / MT)   // 782
#define EDGE_TILES (EE / MT)              // 9375 (exact)

// smem layout (bytes): A rows 64 x 272B (hi, lo), W rows 128 x 272B (hi, lo)
#define SA_HI 0
#define SA_LO 17408
#define SW_HI 34816
#define SW_LO 69632
#define SMEM_BYTES 104448

// ---------------- scratch (device globals; no allocation allowed) ----------
__device__ float g_Ah[NN * DD];
__device__ float g_Bh[NN * DD];
__device__ float g_Dh[NN * DD];
__device__ float g_Eh[NN * DD];
__device__ float g_num[NN * DD];
__device__ float g_den[NN * DD];
__device__ float g_sum[2 * NG * DD];
__device__ float g_sq[2 * NG * DD];
__device__ float g_mean[2 * NG * DD];
__device__ float g_rstd[2 * NG * DD];
__device__ __nv_bfloat16 g_Wt_hi[5 * DD * DD];   // transposed: [l][n][k]
__device__ __nv_bfloat16 g_Wt_lo[5 * DD * DD];

// ---------------- helpers ----------------------------------------------------
__device__ __forceinline__ uint32_t smem_u32(const void* p) {
    uint32_t a;
    asm("{ .reg .u64 t; cvta.to.shared.u64 t, %1; cvt.u32.u64 %0, t; }" : "=r"(a) : "l"(p));
    return a;
}
__device__ __forceinline__ void ldsm4(uint32_t a[4], uint32_t addr) {
    asm volatile("ldmatrix.sync.aligned.m8n8.x4.shared.b16 {%0,%1,%2,%3}, [%4];"
                 : "=r"(a[0]), "=r"(a[1]), "=r"(a[2]), "=r"(a[3]) : "r"(addr));
}
__device__ __forceinline__ void mma16816(float c[4], const uint32_t a[4],
                                         uint32_t b0, uint32_t b1) {
    asm volatile("mma.sync.aligned.m16n8k16.row.col.f32.bf16.bf16.f32 "
                 "{%0,%1,%2,%3}, {%4,%5,%6,%7}, {%8,%9}, {%0,%1,%2,%3};"
                 : "+f"(c[0]), "+f"(c[1]), "+f"(c[2]), "+f"(c[3])
                 : "r"(a[0]), "r"(a[1]), "r"(a[2]), "r"(a[3]), "r"(b0), "r"(b1));
}
__device__ __forceinline__ void redv4(float* p, float4 v) {
    asm volatile("red.global.add.v4.f32 [%0], {%1,%2,%3,%4};"
                 :: "l"(p), "f"(v.x), "f"(v.y), "f"(v.z), "f"(v.w) : "memory");
}

// ---------------- zero scratch ----------------------------------------------
__global__ void zero_kernel() {
    const int nnd = NN * DD;
    const int total = 2 * nnd + 2 * 2 * NG * DD;
    for (int i = blockIdx.x * blockDim.x + threadIdx.x; i < total;
         i += gridDim.x * blockDim.x) {
        if (i < nnd)           g_num[i] = 0.f;
        else if (i < 2 * nnd)  g_den[i - nnd] = 0.f;
        else {
            int j = i - 2 * nnd;
            if (j < 2 * NG * DD) g_sum[j] = 0.f;
            else                 g_sq[j - 2 * NG * DD] = 0.f;
        }
    }
}

// transpose + split W: Wt[l][n][k] = W[l][k][n]
__global__ void splitW_kernel(const float* __restrict__ W) {
    int i = blockIdx.x * blockDim.x + threadIdx.x;
    if (i >= 5 * DD * DD) return;
    int l = i >> 14, j = i & 16383, n = j >> 7, k = j & 127;
    float v = W[(l << 14) + (k << 7) + n];
    __nv_bfloat16 h = __float2bfloat16_rn(v);
    g_Wt_hi[i] = h;
    g_Wt_lo[i] = __float2bfloat16_rn(v - __bfloat162float(h));
}

// ---------------- W loader (once per CTA) ------------------------------------
__device__ __forceinline__ void load_W(char* sm, const __nv_bfloat16* __restrict__ Wh,
                                       const __nv_bfloat16* __restrict__ Wl) {
    const uint32_t* WH = (const uint32_t*)Wh;
    const uint32_t* WL = (const uint32_t*)Wl;
    for (int u = threadIdx.x; u < 128 * 64; u += 256) {
        int r = u >> 6, kk = u & 63;
        *(uint32_t*)(sm + SW_HI + r * 272 + kk * 4) = WH[u];
        *(uint32_t*)(sm + SW_LO + r * 272 + kk * 4) = WL[u];
    }
}

// ---------------- A-tile prefetch (f32 -> regs) and commit (regs -> bf16 smem)
__device__ __forceinline__ void prefetch_tile(const float* __restrict__ X,
                                              long tile, int M, float2 pf[16]) {
    const float2* X2 = (const float2*)X;
    const int t = threadIdx.x;
#pragma unroll
    for (int j = 0; j < 16; j++) {
        int u = t + j * 256;
        int r = u >> 6, kk = u & 63;
        long grow = tile * MT + r;
        pf[j] = (grow < M) ? X2[grow * 64 + kk] : make_float2(0.f, 0.f);
    }
}
__device__ __forceinline__ void commit_tile(char* sm, const float2 pf[16]) {
    const int t = threadIdx.x;
#pragma unroll
    for (int j = 0; j < 16; j++) {
        int u = t + j * 256;
        int r = u >> 6, kk = u & 63;
        __nv_bfloat16 hx = __float2bfloat16_rn(pf[j].x);
        __nv_bfloat16 hy = __float2bfloat16_rn(pf[j].y);
        __nv_bfloat16 lx = __float2bfloat16_rn(pf[j].x - __bfloat162float(hx));
        __nv_bfloat16 ly = __float2bfloat16_rn(pf[j].y - __bfloat162float(hy));
        *(__nv_bfloat162*)(sm + SA_HI + r * 272 + kk * 4) = __nv_bfloat162(hx, hy);
        *(__nv_bfloat162*)(sm + SA_LO + r * 272 + kk * 4) = __nv_bfloat162(lx, ly);
    }
}

// ---------------- warp-mma compute: 64x128 tile, warp = 32x32 ----------------
__device__ __forceinline__ void mma_compute(uint32_t smb, float c[2][4][4]) {
    const int lane = threadIdx.x & 31;
    const int w = threadIdx.x >> 5;
    const int m0 = (w & 1) * 32, n0 = (w >> 1) * 32;
#pragma unroll
    for (int m = 0; m < 2; m++)
#pragma unroll
        for (int n = 0; n < 4; n++)
#pragma unroll
            for (int i = 0; i < 4; i++) c[m][n][i] = 0.f;

    const uint32_t aBase = smb + SA_HI + (m0 + (lane & 15)) * 272 + (lane >> 4) * 16;
    const uint32_t bBase = smb + SW_HI +
        (n0 + (lane & 7) + ((lane >> 4) & 1) * 8) * 272 + ((lane >> 3) & 1) * 16;

#pragma unroll
    for (int k = 0; k < 8; k++) {
        uint32_t aH0[4], aH1[4], aL0[4], aL1[4];
        ldsm4(aH0, aBase + k * 32);
        ldsm4(aH1, aBase + 16 * 272 + k * 32);
        ldsm4(aL0, aBase + (SA_LO - SA_HI) + k * 32);
        ldsm4(aL1, aBase + (SA_LO - SA_HI) + 16 * 272 + k * 32);
#pragma unroll
        for (int np = 0; np < 2; np++) {
            uint32_t bH[4], bL[4];
            ldsm4(bH, bBase + np * 16 * 272 + k * 32);
            ldsm4(bL, bBase + (SW_LO - SW_HI) + np * 16 * 272 + k * 32);
#pragma unroll
            for (int nn = 0; nn < 2; nn++) {
                const int nc = np * 2 + nn;
                mma16816(c[0][nc], aH0, bH[nn * 2], bH[nn * 2 + 1]);
                mma16816(c[1][nc], aH1, bH[nn * 2], bH[nn * 2 + 1]);
                mma16816(c[0][nc], aL0, bH[nn * 2], bH[nn * 2 + 1]);
                mma16816(c[1][nc], aL1, bH[nn * 2], bH[nn * 2 + 1]);
                mma16816(c[0][nc], aH0, bL[nn * 2], bL[nn * 2 + 1]);
                mma16816(c[1][nc], aH1, bL[nn * 2], bL[nn * 2 + 1]);
            }
        }
    }
}

// ---------------- node GEMMs: persistent tiles, layer = blockIdx.y -----------
__global__ void __launch_bounds__(256, 2) node_gemm(const float* __restrict__ h,
                                                    const float* __restrict__ b) {
    extern __shared__ __align__(16) char sm[];
    const int lmap[4] = {0, 1, 3, 4};
    const int l = lmap[blockIdx.y];
    float* out = (blockIdx.y == 0) ? g_Ah : (blockIdx.y == 1) ? g_Bh
               : (blockIdx.y == 2) ? g_Dh : g_Eh;
    load_W(sm, g_Wt_hi + l * DD * DD, g_Wt_lo + l * DD * DD);

    const uint32_t smb = smem_u32(sm);
    const float* bias = b + l * DD;
    const int lane = threadIdx.x & 31, w = threadIdx.x >> 5;
    const int m0 = (w & 1) * 32, n0 = (w >> 1) * 32;
    const int tig = lane & 3, gg = lane >> 2;

    float2 pf[16];
    long tile = blockIdx.x;
    if (tile < NODE_TILES) prefetch_tile(h, tile, NN, pf);
    for (; tile < NODE_TILES; tile += gridDim.x) {
        commit_tile(sm, pf);
        __syncthreads();
        long nt = tile + gridDim.x;
        if (nt < NODE_TILES) prefetch_tile(h, nt, NN, pf);

        float c[2][4][4];
        mma_compute(smb, c);

#pragma unroll
        for (int m = 0; m < 2; m++) {
            long r0 = tile * MT + m0 + m * 16 + gg;
#pragma unroll
            for (int n = 0; n < 4; n++) {
                int col = n0 + n * 8 + tig * 2;
                float2 bv = *(const float2*)(bias + col);
                if (r0 < NN)
                    *(float2*)(out + r0 * DD + col) =
                        make_float2(c[m][n][0] + bv.x, c[m][n][1] + bv.y);
                if (r0 + 8 < NN)
                    *(float2*)(out + (r0 + 8) * DD + col) =
                        make_float2(c[m][n][2] + bv.x, c[m][n][3] + bv.y);
            }
        }
        __syncthreads();   // all ldsm done before next commit overwrites A
    }
}

// ---------------- edge GEMM: persistent tiles + fused epilogue ---------------
__global__ void __launch_bounds__(256, 2) edge_gemm(const float* __restrict__ e,
        const float* __restrict__ b2, const int* __restrict__ src,
        const int* __restrict__ dst, const float* __restrict__ snorm_e,
        float* __restrict__ eout) {
    extern __shared__ __align__(16) char sm[];
    load_W(sm, g_Wt_hi + 2 * DD * DD, g_Wt_lo + 2 * DD * DD);

    const uint32_t smb = smem_u32(sm);
    float* sD = (float*)sm;   // 64 rows x 132 floats (reuses A region)
    const int lane = threadIdx.x & 31, w = threadIdx.x >> 5;
    const int m0 = (w & 1) * 32, n0 = (w >> 1) * 32;
    const int tig = lane & 3, gg = lane >> 2;
    const float se = snorm_e[0];
    const float4 bb = ((const float4*)b2)[lane];

    int gcur = -1;
    float4 s4 = make_float4(0, 0, 0, 0), q4 = make_float4(0, 0, 0, 0);

    float2 pf[16];
    long tile = blockIdx.x;
    if (tile < EDGE_TILES) prefetch_tile(e, tile, EE, pf);
    for (; tile < EDGE_TILES; tile += gridDim.x) {
        commit_tile(sm, pf);
        __syncthreads();
        long nt = tile + gridDim.x;
        if (nt < EDGE_TILES) prefetch_tile(e, nt, EE, pf);

        float c[2][4][4];
        mma_compute(smb, c);
        __syncthreads();   // before sD overwrites the A region

#pragma unroll
        for (int m = 0; m < 2; m++) {
            int r = m0 + m * 16 + gg;
#pragma unroll
            for (int n = 0; n < 4; n++) {
                int col = n0 + n * 8 + tig * 2;
                *(float2*)(sD + r * 132 + col) = make_float2(c[m][n][0], c[m][n][1]);
                *(float2*)(sD + (r + 8) * 132 + col) = make_float2(c[m][n][2], c[m][n][3]);
            }
        }
        __syncthreads();

#pragma unroll 1
        for (int r = 0; r < 8; r++) {
            const int row = w * 8 + r;
            const long grow = tile * MT + row;
            const int s = __ldg(&src[grow]);
            const int d = __ldg(&dst[grow]);
            float4 dv = *(float4*)(sD + row * 132 + lane * 4);
            float4 dh = ((const float4*)g_Dh)[(size_t)s * 32 + lane];
            float4 eh = ((const float4*)g_Eh)[(size_t)d * 32 + lane];
            float4 bh = ((const float4*)g_Bh)[(size_t)s * 32 + lane];
            float ex = dv.x + bb.x + dh.x + eh.x;
            float ey = dv.y + bb.y + dh.y + eh.y;
            float ez = dv.z + bb.z + dh.z + eh.z;
            float ew = dv.w + bb.w + dh.w + eh.w;
            float4 eo = make_float4(ex * se, ey * se, ez * se, ew * se);
            ((float4*)eout)[(size_t)grow * 32 + lane] = eo;
            float sx = 1.f / (1.f + __expf(-ex));
            float sy = 1.f / (1.f + __expf(-ey));
            float sz = 1.f / (1.f + __expf(-ez));
            float sv = 1.f / (1.f + __expf(-ew));
            redv4(&g_num[d * DD + lane * 4],
                  make_float4(sx * bh.x, sy * bh.y, sz * bh.z, sv * bh.w));
            redv4(&g_den[d * DD + lane * 4], make_float4(sx, sy, sz, sv));
            const int gid = (int)(grow / GNE);
            if (gid != gcur) {
                if (gcur >= 0) {
                    redv4(&g_sum[NG * DD + gcur * DD + lane * 4], s4);
                    redv4(&g_sq[NG * DD + gcur * DD + lane * 4], q4);
                }
                gcur = gid;
                s4 = make_float4(0, 0, 0, 0);
                q4 = make_float4(0, 0, 0, 0);
            }
            s4.x += eo.x; s4.y += eo.y; s4.z += eo.z; s4.w += eo.w;
            q4.x = fmaf(eo.x, eo.x, q4.x); q4.y = fmaf(eo.y, eo.y, q4.y);
            q4.z = fmaf(eo.z, eo.z, q4.z); q4.w = fmaf(eo.w, eo.w, q4.w);
        }
        __syncthreads();   // epilogue reads of sD done before next commit
    }
    if (gcur >= 0) {
        redv4(&g_sum[NG * DD + gcur * DD + lane * 4], s4);
        redv4(&g_sq[NG * DD + gcur * DD + lane * 4], q4);
    }
}

// ---------------- node epilogue (vectorized) ----------------------------------
__global__ void node_epi(const float* __restrict__ h, const float* __restrict__ snorm_n,
                         float* __restrict__ outh) {
    const float sn = snorm_n[0];
    const int tot4 = NN * 32;
    for (int i = blockIdx.x * blockDim.x + threadIdx.x; i < tot4;
         i += gridDim.x * blockDim.x) {
        float4 den = ((const float4*)g_den)[i];
        float4 num = ((const float4*)g_num)[i];
        float4 ah  = ((const float4*)g_Ah)[i];
        float4 hv  = ((const float4*)h)[i];
        float4 o;
        o.x = ((den.x > 0.f) ? (ah.x + num.x / (den.x + EPS_RED)) : hv.x) * sn;
        o.y = ((den.y > 0.f) ? (ah.y + num.y / (den.y + EPS_RED)) : hv.y) * sn;
        o.z = ((den.z > 0.f) ? (ah.z + num.z / (den.z + EPS_RED)) : hv.z) * sn;
        o.w = ((den.w > 0.f) ? (ah.w + num.w / (den.w + EPS_RED)) : hv.w) * sn;
        ((float4*)outh)[i] = o;
    }
}

// ---------------- per-graph per-feature stats for h ----------------------------
__global__ void stats_kernel(const float* __restrict__ x, int size, int statOff) {
    int g = blockIdx.y;
    int per = (size + gridDim.x - 1) / gridDim.x;
    int r0 = blockIdx.x * per;
    int r1 = min(size, r0 + per);
    int f = threadIdx.x;
    const float* base = x + (size_t)g * size * DD;
    float s = 0.f, q = 0.f;
    for (int r = r0; r < r1; r++) {
        float v = base[(size_t)r * DD + f];
        s += v;
        q = fmaf(v, v, q);
    }
    if (r0 < r1) {
        atomicAdd(&g_sum[statOff + g * DD + f], s);
        atomicAdd(&g_sq[statOff + g * DD + f], q);
    }
}

__global__ void meanstd_kernel() {
    int i = blockIdx.x * blockDim.x + threadIdx.x;
    if (i >= 2 * NG * DD) return;
    float n = (i < NG * DD) ? (float)GNH : (float)GNE;
    float s = g_sum[i], q = g_sq[i];
    float mean = s / n;
    float var = (q - s * mean) / (n - 1.f);
    var = fmaxf(var, 0.f);
    g_mean[i] = mean;
    g_rstd[i] = 1.f / (sqrtf(var) + EPS_NORM);
}

// ---------------- finalize (vectorized): graphnorm + relu + residual ----------
__global__ void finalize_kernel(float* __restrict__ io, const float* __restrict__ resid,
                                const float* __restrict__ gamma,
                                const float* __restrict__ beta, int size, int statOff) {
    int g = blockIdx.y;
    size_t base4 = (size_t)g * size * 32;
    int tot4 = size * 32;
    const float4* mean4 = (const float4*)(g_mean + statOff + g * DD);
    const float4* rstd4 = (const float4*)(g_rstd + statOff + g * DD);
    for (int i = blockIdx.x * blockDim.x + threadIdx.x; i < tot4;
         i += gridDim.x * blockDim.x) {
        int f4 = i & 31;
        float4 xv = ((const float4*)io)[base4 + i];
        float4 rv = ((const float4*)resid)[base4 + i];
        float4 ga = ((const float4*)gamma)[f4];
        float4 be = ((const float4*)beta)[f4];
        float4 mn = mean4[f4];
        float4 rs = rstd4[f4];
        float4 o;
        o.x = rv.x + fmaxf(fmaf(ga.x, (xv.x - mn.x) * rs.x, be.x), 0.f);
        o.y = rv.y + fmaxf(fmaf(ga.y, (xv.y - mn.y) * rs.y, be.y), 0.f);
        o.z = rv.z + fmaxf(fmaf(ga.z, (xv.z - mn.z) * rs.z, be.z), 0.f);
        o.w = rv.w + fmaxf(fmaf(ga.w, (xv.w - mn.w) * rs.w, be.w), 0.f);
        ((float4*)io)[base4 + i] = o;
    }
}

// ---------------- launcher -------------------------------------------------------
extern "C" void kernel_launch(void* const* d_in, const int* in_sizes, int n_in,
                              void* d_out, int out_size) {
    const float* h   = (const float*)d_in[0];
    const float* e   = (const float*)d_in[1];
    const int*   src = (const int*)d_in[2];
    const int*   dst = (const int*)d_in[3];
    const float* snn = (const float*)d_in[4];
    const float* sne = (const float*)d_in[5];
    const float* W   = (const float*)d_in[6];
    const float* b   = (const float*)d_in[7];
    const float* gam_h = (const float*)d_in[8];
    const float* bet_h = (const float*)d_in[9];
    const float* gam_e = (const float*)d_in[10];
    const float* bet_e = (const float*)d_in[11];

    float* out_h = (float*)d_out;
    float* out_e = out_h + (size_t)NN * DD;

    cudaFuncSetAttribute((const void*)node_gemm,
                         cudaFuncAttributeMaxDynamicSharedMemorySize, SMEM_BYTES);
    cudaFuncSetAttribute((const void*)edge_gemm,
                         cudaFuncAttributeMaxDynamicSharedMemorySize, SMEM_BYTES);

    zero_kernel<<<1024, 256>>>();
    splitW_kernel<<<(5 * DD * DD + 255) / 256, 256>>>(W);

    node_gemm<<<dim3(74, 4), 256, SMEM_BYTES>>>(h, b);
    edge_gemm<<<296, 256, SMEM_BYTES>>>(e, b + 2 * DD, src, dst, sne, out_e);

    node_epi<<<2048, 256>>>(h, snn, out_h);

    stats_kernel<<<dim3(64, NG), 128>>>(out_h, GNH, 0);
    meanstd_kernel<<<10, 256>>>();

    finalize_kernel<<<dim3(160, NG), 256>>>(out_h, h, gam_h, bet_h, GNH, 0);
    finalize_kernel<<<dim3(1024, NG), 256>>>(out_e, e, gam_e, bet_e, GNE, NG * DD);
}

// round 5
// speedup vs baseline: 1.9864x; 1.0538x over previous
#include <cuda_runtime.h>
#include <cuda_bf16.h>
#include <math.h>
#include <stdint.h>

#define NN 50000
#define EE 600000
#define DD 128
#define GNH 5000
#define GNE 60000
#define NG 10
#define EPS_NORM 1e-5f
#define EPS_RED  1e-6f

#define MT 64
#define NODE_TILES ((NN + MT - 1) / MT)   // 782
#define EDGE_TILES (EE / MT)              // 9375 (exact)

// smem layout (bytes): A rows 64 x 272B (hi, lo), W rows 128 x 272B (hi, lo)
#define SA_HI 0
#define SA_LO 17408
#define SW_HI 34816
#define SW_LO 69632
#define SMEM_BYTES 104448

// ---------------- scratch (device globals; no allocation allowed) ----------
__device__ float g_Ah[NN * DD];
__device__ float g_DB[NN * 256];          // [node][0:128)=Dh, [128:256)=Bh (both src-indexed)
__device__ float g_Eh[NN * DD];
__device__ float g_num[NN * DD];
__device__ float g_den[NN * DD];
__device__ float g_sum[2 * NG * DD];
__device__ float g_sq[2 * NG * DD];
__device__ float g_mean[2 * NG * DD];
__device__ float g_rstd[2 * NG * DD];
__device__ __nv_bfloat16 g_Wt_hi[5 * DD * DD];   // transposed: [l][n][k]
__device__ __nv_bfloat16 g_Wt_lo[5 * DD * DD];

// ---------------- helpers ----------------------------------------------------
__device__ __forceinline__ uint32_t smem_u32(const void* p) {
    uint32_t a;
    asm("{ .reg .u64 t; cvta.to.shared.u64 t, %1; cvt.u32.u64 %0, t; }" : "=r"(a) : "l"(p));
    return a;
}
__device__ __forceinline__ void ldsm4(uint32_t a[4], uint32_t addr) {
    asm volatile("ldmatrix.sync.aligned.m8n8.x4.shared.b16 {%0,%1,%2,%3}, [%4];"
                 : "=r"(a[0]), "=r"(a[1]), "=r"(a[2]), "=r"(a[3]) : "r"(addr));
}
__device__ __forceinline__ void mma16816(float c[4], const uint32_t a[4],
                                         uint32_t b0, uint32_t b1) {
    asm volatile("mma.sync.aligned.m16n8k16.row.col.f32.bf16.bf16.f32 "
                 "{%0,%1,%2,%3}, {%4,%5,%6,%7}, {%8,%9}, {%0,%1,%2,%3};"
                 : "+f"(c[0]), "+f"(c[1]), "+f"(c[2]), "+f"(c[3])
                 : "r"(a[0]), "r"(a[1]), "r"(a[2]), "r"(a[3]), "r"(b0), "r"(b1));
}
__device__ __forceinline__ void redv4(float* p, float4 v) {
    asm volatile("red.global.add.v4.f32 [%0], {%1,%2,%3,%4};"
                 :: "l"(p), "f"(v.x), "f"(v.y), "f"(v.z), "f"(v.w) : "memory");
}
// sigmoid via single-MUFU tanh: sig(x) = 0.5*tanh(x/2) + 0.5
__device__ __forceinline__ float sigt(float x) {
    float t;
    asm("tanh.approx.f32 %0, %1;" : "=f"(t) : "f"(x * 0.5f));
    return fmaf(t, 0.5f, 0.5f);
}

// ---------------- zero scratch ----------------------------------------------
__global__ void zero_kernel() {
    const int nnd = NN * DD;
    const int total = 2 * nnd + 2 * 2 * NG * DD;
    for (int i = blockIdx.x * blockDim.x + threadIdx.x; i < total;
         i += gridDim.x * blockDim.x) {
        if (i < nnd)           g_num[i] = 0.f;
        else if (i < 2 * nnd)  g_den[i - nnd] = 0.f;
        else {
            int j = i - 2 * nnd;
            if (j < 2 * NG * DD) g_sum[j] = 0.f;
            else                 g_sq[j - 2 * NG * DD] = 0.f;
        }
    }
}

// transpose + split W: Wt[l][n][k] = W[l][k][n]
__global__ void splitW_kernel(const float* __restrict__ W) {
    int i = blockIdx.x * blockDim.x + threadIdx.x;
    if (i >= 5 * DD * DD) return;
    int l = i >> 14, j = i & 16383, n = j >> 7, k = j & 127;
    float v = W[(l << 14) + (k << 7) + n];
    __nv_bfloat16 h = __float2bfloat16_rn(v);
    g_Wt_hi[i] = h;
    g_Wt_lo[i] = __float2bfloat16_rn(v - __bfloat162float(h));
}

// ---------------- W loader (once per CTA) ------------------------------------
__device__ __forceinline__ void load_W(char* sm, const __nv_bfloat16* __restrict__ Wh,
                                       const __nv_bfloat16* __restrict__ Wl) {
    const uint32_t* WH = (const uint32_t*)Wh;
    const uint32_t* WL = (const uint32_t*)Wl;
    for (int u = threadIdx.x; u < 128 * 64; u += 256) {
        int r = u >> 6, kk = u & 63;
        *(uint32_t*)(sm + SW_HI + r * 272 + kk * 4) = WH[u];
        *(uint32_t*)(sm + SW_LO + r * 272 + kk * 4) = WL[u];
    }
}

// ---------------- A-tile prefetch (f32 -> regs) and commit (regs -> bf16 smem)
__device__ __forceinline__ void prefetch_tile(const float* __restrict__ X,
                                              long tile, int M, float2 pf[16]) {
    const float2* X2 = (const float2*)X;
    const int t = threadIdx.x;
#pragma unroll
    for (int j = 0; j < 16; j++) {
        int u = t + j * 256;
        int r = u >> 6, kk = u & 63;
        long grow = tile * MT + r;
        pf[j] = (grow < M) ? X2[grow * 64 + kk] : make_float2(0.f, 0.f);
    }
}
__device__ __forceinline__ void commit_tile(char* sm, const float2 pf[16]) {
    const int t = threadIdx.x;
#pragma unroll
    for (int j = 0; j < 16; j++) {
        int u = t + j * 256;
        int r = u >> 6, kk = u & 63;
        __nv_bfloat16 hx = __float2bfloat16_rn(pf[j].x);
        __nv_bfloat16 hy = __float2bfloat16_rn(pf[j].y);
        __nv_bfloat16 lx = __float2bfloat16_rn(pf[j].x - __bfloat162float(hx));
        __nv_bfloat16 ly = __float2bfloat16_rn(pf[j].y - __bfloat162float(hy));
        *(__nv_bfloat162*)(sm + SA_HI + r * 272 + kk * 4) = __nv_bfloat162(hx, hy);
        *(__nv_bfloat162*)(sm + SA_LO + r * 272 + kk * 4) = __nv_bfloat162(lx, ly);
    }
}

// ---------------- warp-mma compute: 64x128 tile, warp = 32x32 ----------------
__device__ __forceinline__ void mma_compute(uint32_t smb, float c[2][4][4]) {
    const int lane = threadIdx.x & 31;
    const int w = threadIdx.x >> 5;
    const int m0 = (w & 1) * 32, n0 = (w >> 1) * 32;
#pragma unroll
    for (int m = 0; m < 2; m++)
#pragma unroll
        for (int n = 0; n < 4; n++)
#pragma unroll
            for (int i = 0; i < 4; i++) c[m][n][i] = 0.f;

    const uint32_t aBase = smb + SA_HI + (m0 + (lane & 15)) * 272 + (lane >> 4) * 16;
    const uint32_t bBase = smb + SW_HI +
        (n0 + (lane & 7) + ((lane >> 4) & 1) * 8) * 272 + ((lane >> 3) & 1) * 16;

#pragma unroll
    for (int k = 0; k < 8; k++) {
        uint32_t aH0[4], aH1[4], aL0[4], aL1[4];
        ldsm4(aH0, aBase + k * 32);
        ldsm4(aH1, aBase + 16 * 272 + k * 32);
        ldsm4(aL0, aBase + (SA_LO - SA_HI) + k * 32);
        ldsm4(aL1, aBase + (SA_LO - SA_HI) + 16 * 272 + k * 32);
#pragma unroll
        for (int np = 0; np < 2; np++) {
            uint32_t bH[4], bL[4];
            ldsm4(bH, bBase + np * 16 * 272 + k * 32);
            ldsm4(bL, bBase + (SW_LO - SW_HI) + np * 16 * 272 + k * 32);
#pragma unroll
            for (int nn = 0; nn < 2; nn++) {
                const int nc = np * 2 + nn;
                mma16816(c[0][nc], aH0, bH[nn * 2], bH[nn * 2 + 1]);
                mma16816(c[1][nc], aH1, bH[nn * 2], bH[nn * 2 + 1]);
                mma16816(c[0][nc], aL0, bH[nn * 2], bH[nn * 2 + 1]);
                mma16816(c[1][nc], aL1, bH[nn * 2], bH[nn * 2 + 1]);
                mma16816(c[0][nc], aH0, bL[nn * 2], bL[nn * 2 + 1]);
                mma16816(c[1][nc], aH1, bL[nn * 2], bL[nn * 2 + 1]);
            }
        }
    }
}

// ---------------- node GEMMs: persistent tiles, layer = blockIdx.y -----------
// y=0 -> Ah (stride 128); y=1 -> Bh into g_DB+128 (stride 256);
// y=2 -> Dh into g_DB+0 (stride 256); y=3 -> Eh (stride 128)
__global__ void __launch_bounds__(256, 2) node_gemm(const float* __restrict__ h,
                                                    const float* __restrict__ b) {
    extern __shared__ __align__(16) char sm[];
    const int lmap[4] = {0, 1, 3, 4};
    const int l = lmap[blockIdx.y];
    float* out;
    int ostride;
    if (blockIdx.y == 0)      { out = g_Ah;      ostride = 128; }
    else if (blockIdx.y == 1) { out = g_DB + 128; ostride = 256; }
    else if (blockIdx.y == 2) { out = g_DB;      ostride = 256; }
    else                      { out = g_Eh;      ostride = 128; }
    load_W(sm, g_Wt_hi + l * DD * DD, g_Wt_lo + l * DD * DD);

    const uint32_t smb = smem_u32(sm);
    const float* bias = b + l * DD;
    const int lane = threadIdx.x & 31, w = threadIdx.x >> 5;
    const int m0 = (w & 1) * 32, n0 = (w >> 1) * 32;
    const int tig = lane & 3, gg = lane >> 2;

    float2 pf[16];
    long tile = blockIdx.x;
    if (tile < NODE_TILES) prefetch_tile(h, tile, NN, pf);
    for (; tile < NODE_TILES; tile += gridDim.x) {
        commit_tile(sm, pf);
        __syncthreads();
        long nt = tile + gridDim.x;
        if (nt < NODE_TILES) prefetch_tile(h, nt, NN, pf);

        float c[2][4][4];
        mma_compute(smb, c);

#pragma unroll
        for (int m = 0; m < 2; m++) {
            long r0 = tile * MT + m0 + m * 16 + gg;
#pragma unroll
            for (int n = 0; n < 4; n++) {
                int col = n0 + n * 8 + tig * 2;
                float2 bv = *(const float2*)(bias + col);
                if (r0 < NN)
                    *(float2*)(out + r0 * ostride + col) =
                        make_float2(c[m][n][0] + bv.x, c[m][n][1] + bv.y);
                if (r0 + 8 < NN)
                    *(float2*)(out + (r0 + 8) * ostride + col) =
                        make_float2(c[m][n][2] + bv.x, c[m][n][3] + bv.y);
            }
        }
        __syncthreads();   // all ldsm done before next commit overwrites A
    }
}

// ---------------- edge GEMM: persistent tiles + fused epilogue ---------------
__global__ void __launch_bounds__(256, 2) edge_gemm(const float* __restrict__ e,
        const float* __restrict__ b2, const int* __restrict__ src,
        const int* __restrict__ dst, const float* __restrict__ snorm_e,
        float* __restrict__ eout) {
    extern __shared__ __align__(16) char sm[];
    load_W(sm, g_Wt_hi + 2 * DD * DD, g_Wt_lo + 2 * DD * DD);

    const uint32_t smb = smem_u32(sm);
    float* sD = (float*)sm;   // 64 rows x 132 floats (reuses A region)
    const int lane = threadIdx.x & 31, w = threadIdx.x >> 5;
    const int m0 = (w & 1) * 32, n0 = (w >> 1) * 32;
    const int tig = lane & 3, gg = lane >> 2;
    const float se = snorm_e[0];
    const float4 bb = ((const float4*)b2)[lane];
    const float4* DB = (const float4*)g_DB;

    int gcur = -1;
    float4 s4 = make_float4(0, 0, 0, 0), q4 = make_float4(0, 0, 0, 0);

    float2 pf[16];
    long tile = blockIdx.x;
    if (tile < EDGE_TILES) prefetch_tile(e, tile, EE, pf);
    for (; tile < EDGE_TILES; tile += gridDim.x) {
        commit_tile(sm, pf);
        __syncthreads();
        long nt = tile + gridDim.x;
        if (nt < EDGE_TILES) prefetch_tile(e, nt, EE, pf);

        float c[2][4][4];
        mma_compute(smb, c);
        __syncthreads();   // before sD overwrites the A region

#pragma unroll
        for (int m = 0; m < 2; m++) {
            int r = m0 + m * 16 + gg;
#pragma unroll
            for (int n = 0; n < 4; n++) {
                int col = n0 + n * 8 + tig * 2;
                *(float2*)(sD + r * 132 + col) = make_float2(c[m][n][0], c[m][n][1]);
                *(float2*)(sD + (r + 8) * 132 + col) = make_float2(c[m][n][2], c[m][n][3]);
            }
        }
        __syncthreads();

#pragma unroll 1
        for (int r = 0; r < 8; r++) {
            const int row = w * 8 + r;
            const long grow = tile * MT + row;
            const int s = __ldg(&src[grow]);
            const int d = __ldg(&dst[grow]);
            float4 dv = *(float4*)(sD + row * 132 + lane * 4);
            float4 dh = DB[(size_t)s * 64 + lane];
            float4 bh = DB[(size_t)s * 64 + 32 + lane];
            float4 eh = ((const float4*)g_Eh)[(size_t)d * 32 + lane];
            float ex = dv.x + bb.x + dh.x + eh.x;
            float ey = dv.y + bb.y + dh.y + eh.y;
            float ez = dv.z + bb.z + dh.z + eh.z;
            float ew = dv.w + bb.w + dh.w + eh.w;
            float4 eo = make_float4(ex * se, ey * se, ez * se, ew * se);
            ((float4*)eout)[(size_t)grow * 32 + lane] = eo;
            float sx = sigt(ex);
            float sy = sigt(ey);
            float sz = sigt(ez);
            float sv = sigt(ew);
            redv4(&g_num[d * DD + lane * 4],
                  make_float4(sx * bh.x, sy * bh.y, sz * bh.z, sv * bh.w));
            redv4(&g_den[d * DD + lane * 4], make_float4(sx, sy, sz, sv));
            const int gid = (int)(grow / GNE);
            if (gid != gcur) {
                if (gcur >= 0) {
                    redv4(&g_sum[NG * DD + gcur * DD + lane * 4], s4);
                    redv4(&g_sq[NG * DD + gcur * DD + lane * 4], q4);
                }
                gcur = gid;
                s4 = make_float4(0, 0, 0, 0);
                q4 = make_float4(0, 0, 0, 0);
            }
            s4.x += eo.x; s4.y += eo.y; s4.z += eo.z; s4.w += eo.w;
            q4.x = fmaf(eo.x, eo.x, q4.x); q4.y = fmaf(eo.y, eo.y, q4.y);
            q4.z = fmaf(eo.z, eo.z, q4.z); q4.w = fmaf(eo.w, eo.w, q4.w);
        }
        __syncthreads();   // epilogue reads of sD done before next commit
    }
    if (gcur >= 0) {
        redv4(&g_sum[NG * DD + gcur * DD + lane * 4], s4);
        redv4(&g_sq[NG * DD + gcur * DD + lane * 4], q4);
    }
}

// ---------------- node epilogue (vectorized) ----------------------------------
__global__ void node_epi(const float* __restrict__ h, const float* __restrict__ snorm_n,
                         float* __restrict__ outh) {
    const float sn = snorm_n[0];
    const int tot4 = NN * 32;
    for (int i = blockIdx.x * blockDim.x + threadIdx.x; i < tot4;
         i += gridDim.x * blockDim.x) {
        float4 den = ((const float4*)g_den)[i];
        float4 num = ((const float4*)g_num)[i];
        float4 ah  = ((const float4*)g_Ah)[i];
        float4 hv  = ((const float4*)h)[i];
        float4 o;
        o.x = ((den.x > 0.f) ? (ah.x + num.x / (den.x + EPS_RED)) : hv.x) * sn;
        o.y = ((den.y > 0.f) ? (ah.y + num.y / (den.y + EPS_RED)) : hv.y) * sn;
        o.z = ((den.z > 0.f) ? (ah.z + num.z / (den.z + EPS_RED)) : hv.z) * sn;
        o.w = ((den.w > 0.f) ? (ah.w + num.w / (den.w + EPS_RED)) : hv.w) * sn;
        ((float4*)outh)[i] = o;
    }
}

// ---------------- per-graph per-feature stats for h ----------------------------
__global__ void stats_kernel(const float* __restrict__ x, int size, int statOff) {
    int g = blockIdx.y;
    int per = (size + gridDim.x - 1) / gridDim.x;
    int r0 = blockIdx.x * per;
    int r1 = min(size, r0 + per);
    int f = threadIdx.x;
    const float* base = x + (size_t)g * size * DD;
    float s = 0.f, q = 0.f;
    for (int r = r0; r < r1; r++) {
        float v = base[(size_t)r * DD + f];
        s += v;
        q = fmaf(v, v, q);
    }
    if (r0 < r1) {
        atomicAdd(&g_sum[statOff + g * DD + f], s);
        atomicAdd(&g_sq[statOff + g * DD + f], q);
    }
}

__global__ void meanstd_kernel() {
    int i = blockIdx.x * blockDim.x + threadIdx.x;
    if (i >= 2 * NG * DD) return;
    float n = (i < NG * DD) ? (float)GNH : (float)GNE;
    float s = g_sum[i], q = g_sq[i];
    float mean = s / n;
    float var = (q - s * mean) / (n - 1.f);
    var = fmaxf(var, 0.f);
    g_mean[i] = mean;
    g_rstd[i] = 1.f / (sqrtf(var) + EPS_NORM);
}

// ---------------- finalize (vectorized): graphnorm + relu + residual ----------
__global__ void finalize_kernel(float* __restrict__ io, const float* __restrict__ resid,
                                const float* __restrict__ gamma,
                                const float* __restrict__ beta, int size, int statOff) {
    int g = blockIdx.y;
    size_t base4 = (size_t)g * size * 32;
    int tot4 = size * 32;
    const float4* mean4 = (const float4*)(g_mean + statOff + g * DD);
    const float4* rstd4 = (const float4*)(g_rstd + statOff + g * DD);
    for (int i = blockIdx.x * blockDim.x + threadIdx.x; i < tot4;
         i += gridDim.x * blockDim.x) {
        int f4 = i & 31;
        float4 xv = ((const float4*)io)[base4 + i];
        float4 rv = ((const float4*)resid)[base4 + i];
        float4 ga = ((const float4*)gamma)[f4];
        float4 be = ((const float4*)beta)[f4];
        float4 mn = mean4[f4];
        float4 rs = rstd4[f4];
        float4 o;
        o.x = rv.x + fmaxf(fmaf(ga.x, (xv.x - mn.x) * rs.x, be.x), 0.f);
        o.y = rv.y + fmaxf(fmaf(ga.y, (xv.y - mn.y) * rs.y, be.y), 0.f);
        o.z = rv.z + fmaxf(fmaf(ga.z, (xv.z - mn.z) * rs.z, be.z), 0.f);
        o.w = rv.w + fmaxf(fmaf(ga.w, (xv.w - mn.w) * rs.w, be.w), 0.f);
        ((float4*)io)[base4 + i] = o;
    }
}

// ---------------- launcher -------------------------------------------------------
extern "C" void kernel_launch(void* const* d_in, const int* in_sizes, int n_in,
                              void* d_out, int out_size) {
    const float* h   = (const float*)d_in[0];
    const float* e   = (const float*)d_in[1];
    const int*   src = (const int*)d_in[2];
    const int*   dst = (const int*)d_in[3];
    const float* snn = (const float*)d_in[4];
    const float* sne = (const float*)d_in[5];
    const float* W   = (const float*)d_in[6];
    const float* b   = (const float*)d_in[7];
    const float* gam_h = (const float*)d_in[8];
    const float* bet_h = (const float*)d_in[9];
    const float* gam_e = (const float*)d_in[10];
    const float* bet_e = (const float*)d_in[11];

    float* out_h = (float*)d_out;
    float* out_e = out_h + (size_t)NN * DD;

    cudaFuncSetAttribute((const void*)node_gemm,
                         cudaFuncAttributeMaxDynamicSharedMemorySize, SMEM_BYTES);
    cudaFuncSetAttribute((const void*)edge_gemm,
                         cudaFuncAttributeMaxDynamicSharedMemorySize, SMEM_BYTES);

    zero_kernel<<<1024, 256>>>();
    splitW_kernel<<<(5 * DD * DD + 255) / 256, 256>>>(W);

    node_gemm<<<dim3(74, 4), 256, SMEM_BYTES>>>(h, b);
    edge_gemm<<<296, 256, SMEM_BYTES>>>(e, b + 2 * DD, src, dst, sne, out_e);

    node_epi<<<2048, 256>>>(h, snn, out_h);

    stats_kernel<<<dim3(64, NG), 128>>>(out_h, GNH, 0);
    meanstd_kernel<<<10, 256>>>();

    finalize_kernel<<<dim3(160, NG), 256>>>(out_h, h, gam_h, bet_h, GNH, 0);
    finalize_kernel<<<dim3(1024, NG), 256>>>(out_e, e, gam_e, bet_e, GNE, NG * DD);
}

// round 6
// speedup vs baseline: 2.1569x; 1.0859x over previous
#include <cuda_runtime.h>
#include <cuda_bf16.h>
#include <math.h>
#include <stdint.h>

#define NN 50000
#define EE 600000
#define DD 128
#define GNH 5000
#define GNE 60000
#define NG 10
#define EPS_NORM 1e-5f
#define EPS_RED  1e-6f

#define MT 64
#define NODE_TILES ((NN + MT - 1) / MT)   // 782
#define EDGE_TILES (EE / MT)              // 9375 (exact)

// smem layout (bytes): A rows 64 x 272B (hi, lo), W rows 128 x 272B (hi, lo)
#define SA_HI 0
#define SA_LO 17408
#define SW_HI 34816
#define SW_LO 69632
#define SMEM_BYTES 104448

// ---------------- scratch (device globals; no allocation allowed) ----------
__device__ float g_Ah[NN * DD];
__device__ float g_DB[NN * 256];          // [node][0:128)=Dh, [128:256)=Bh (both src-indexed)
__device__ float g_Eh[NN * DD];
__device__ float g_num[NN * DD];
__device__ float g_den[NN * DD];
__device__ float g_sum[2 * NG * DD];
__device__ float g_sq[2 * NG * DD];
__device__ float g_mean[2 * NG * DD];
__device__ float g_rstd[2 * NG * DD];
__device__ __nv_bfloat16 g_Wt_hi[5 * DD * DD];   // transposed: [l][n][k]
__device__ __nv_bfloat16 g_Wt_lo[5 * DD * DD];

// ---------------- helpers ----------------------------------------------------
__device__ __forceinline__ uint32_t smem_u32(const void* p) {
    uint32_t a;
    asm("{ .reg .u64 t; cvta.to.shared.u64 t, %1; cvt.u32.u64 %0, t; }" : "=r"(a) : "l"(p));
    return a;
}
__device__ __forceinline__ void ldsm4(uint32_t a[4], uint32_t addr) {
    asm volatile("ldmatrix.sync.aligned.m8n8.x4.shared.b16 {%0,%1,%2,%3}, [%4];"
                 : "=r"(a[0]), "=r"(a[1]), "=r"(a[2]), "=r"(a[3]) : "r"(addr));
}
__device__ __forceinline__ void mma16816(float c[4], const uint32_t a[4],
                                         uint32_t b0, uint32_t b1) {
    asm volatile("mma.sync.aligned.m16n8k16.row.col.f32.bf16.bf16.f32 "
                 "{%0,%1,%2,%3}, {%4,%5,%6,%7}, {%8,%9}, {%0,%1,%2,%3};"
                 : "+f"(c[0]), "+f"(c[1]), "+f"(c[2]), "+f"(c[3])
                 : "r"(a[0]), "r"(a[1]), "r"(a[2]), "r"(a[3]), "r"(b0), "r"(b1));
}
__device__ __forceinline__ void redv4(float* p, float4 v) {
    asm volatile("red.global.add.v4.f32 [%0], {%1,%2,%3,%4};"
                 :: "l"(p), "f"(v.x), "f"(v.y), "f"(v.z), "f"(v.w) : "memory");
}
// sigmoid via single-MUFU tanh: sig(x) = 0.5*tanh(x/2) + 0.5
__device__ __forceinline__ float sigt(float x) {
    float t;
    asm("tanh.approx.f32 %0, %1;" : "=f"(t) : "f"(x * 0.5f));
    return fmaf(t, 0.5f, 0.5f);
}

// ---------------- zero scratch ----------------------------------------------
__global__ void zero_kernel() {
    const int nnd = NN * DD;
    const int total = 2 * nnd + 2 * 2 * NG * DD;
    for (int i = blockIdx.x * blockDim.x + threadIdx.x; i < total;
         i += gridDim.x * blockDim.x) {
        if (i < nnd)           g_num[i] = 0.f;
        else if (i < 2 * nnd)  g_den[i - nnd] = 0.f;
        else {
            int j = i - 2 * nnd;
            if (j < 2 * NG * DD) g_sum[j] = 0.f;
            else                 g_sq[j - 2 * NG * DD] = 0.f;
        }
    }
}

// transpose + split W: Wt[l][n][k] = W[l][k][n]
__global__ void splitW_kernel(const float* __restrict__ W) {
    int i = blockIdx.x * blockDim.x + threadIdx.x;
    if (i >= 5 * DD * DD) return;
    int l = i >> 14, j = i & 16383, n = j >> 7, k = j & 127;
    float v = W[(l << 14) + (k << 7) + n];
    __nv_bfloat16 h = __float2bfloat16_rn(v);
    g_Wt_hi[i] = h;
    g_Wt_lo[i] = __float2bfloat16_rn(v - __bfloat162float(h));
}

// ---------------- W loader (once per CTA) ------------------------------------
__device__ __forceinline__ void load_W(char* sm, const __nv_bfloat16* __restrict__ Wh,
                                       const __nv_bfloat16* __restrict__ Wl) {
    const uint32_t* WH = (const uint32_t*)Wh;
    const uint32_t* WL = (const uint32_t*)Wl;
    for (int u = threadIdx.x; u < 128 * 64; u += 256) {
        int r = u >> 6, kk = u & 63;
        *(uint32_t*)(sm + SW_HI + r * 272 + kk * 4) = WH[u];
        *(uint32_t*)(sm + SW_LO + r * 272 + kk * 4) = WL[u];
    }
}

// ---------------- A-tile prefetch (f32 -> regs) and commit (regs -> bf16 smem)
template <bool STREAM>
__device__ __forceinline__ void prefetch_tile(const float* __restrict__ X,
                                              long tile, int M, float2 pf[16]) {
    const float2* X2 = (const float2*)X;
    const int t = threadIdx.x;
#pragma unroll
    for (int j = 0; j < 16; j++) {
        int u = t + j * 256;
        int r = u >> 6, kk = u & 63;
        long grow = tile * MT + r;
        if (grow < M) pf[j] = STREAM ? __ldcs(&X2[grow * 64 + kk]) : X2[grow * 64 + kk];
        else          pf[j] = make_float2(0.f, 0.f);
    }
}
__device__ __forceinline__ void commit_tile(char* sm, const float2 pf[16]) {
    const int t = threadIdx.x;
#pragma unroll
    for (int j = 0; j < 16; j++) {
        int u = t + j * 256;
        int r = u >> 6, kk = u & 63;
        __nv_bfloat16 hx = __float2bfloat16_rn(pf[j].x);
        __nv_bfloat16 hy = __float2bfloat16_rn(pf[j].y);
        __nv_bfloat16 lx = __float2bfloat16_rn(pf[j].x - __bfloat162float(hx));
        __nv_bfloat16 ly = __float2bfloat16_rn(pf[j].y - __bfloat162float(hy));
        *(__nv_bfloat162*)(sm + SA_HI + r * 272 + kk * 4) = __nv_bfloat162(hx, hy);
        *(__nv_bfloat162*)(sm + SA_LO + r * 272 + kk * 4) = __nv_bfloat162(lx, ly);
    }
}

// ---------------- warp-mma compute: 64x128 tile, warp = 32x32 ----------------
__device__ __forceinline__ void mma_compute(uint32_t smb, float c[2][4][4]) {
    const int lane = threadIdx.x & 31;
    const int w = threadIdx.x >> 5;
    const int m0 = (w & 1) * 32, n0 = (w >> 1) * 32;
#pragma unroll
    for (int m = 0; m < 2; m++)
#pragma unroll
        for (int n = 0; n < 4; n++)
#pragma unroll
            for (int i = 0; i < 4; i++) c[m][n][i] = 0.f;

    const uint32_t aBase = smb + SA_HI + (m0 + (lane & 15)) * 272 + (lane >> 4) * 16;
    const uint32_t bBase = smb + SW_HI +
        (n0 + (lane & 7) + ((lane >> 4) & 1) * 8) * 272 + ((lane >> 3) & 1) * 16;

#pragma unroll
    for (int k = 0; k < 8; k++) {
        uint32_t aH0[4], aH1[4], aL0[4], aL1[4];
        ldsm4(aH0, aBase + k * 32);
        ldsm4(aH1, aBase + 16 * 272 + k * 32);
        ldsm4(aL0, aBase + (SA_LO - SA_HI) + k * 32);
        ldsm4(aL1, aBase + (SA_LO - SA_HI) + 16 * 272 + k * 32);
#pragma unroll
        for (int np = 0; np < 2; np++) {
            uint32_t bH[4], bL[4];
            ldsm4(bH, bBase + np * 16 * 272 + k * 32);
            ldsm4(bL, bBase + (SW_LO - SW_HI) + np * 16 * 272 + k * 32);
#pragma unroll
            for (int nn = 0; nn < 2; nn++) {
                const int nc = np * 2 + nn;
                mma16816(c[0][nc], aH0, bH[nn * 2], bH[nn * 2 + 1]);
                mma16816(c[1][nc], aH1, bH[nn * 2], bH[nn * 2 + 1]);
                mma16816(c[0][nc], aL0, bH[nn * 2], bH[nn * 2 + 1]);
                mma16816(c[1][nc], aL1, bH[nn * 2], bH[nn * 2 + 1]);
                mma16816(c[0][nc], aH0, bL[nn * 2], bL[nn * 2 + 1]);
                mma16816(c[1][nc], aH1, bL[nn * 2], bL[nn * 2 + 1]);
            }
        }
    }
}

// ---------------- node GEMMs: persistent tiles, layer = blockIdx.y -----------
// y=0 -> Ah (stride 128); y=1 -> Bh into g_DB+128 (stride 256);
// y=2 -> Dh into g_DB+0 (stride 256); y=3 -> Eh (stride 128)
__global__ void __launch_bounds__(256, 2) node_gemm(const float* __restrict__ h,
                                                    const float* __restrict__ b) {
    extern __shared__ __align__(16) char sm[];
    const int lmap[4] = {0, 1, 3, 4};
    const int l = lmap[blockIdx.y];
    float* out;
    int ostride;
    if (blockIdx.y == 0)      { out = g_Ah;       ostride = 128; }
    else if (blockIdx.y == 1) { out = g_DB + 128; ostride = 256; }
    else if (blockIdx.y == 2) { out = g_DB;       ostride = 256; }
    else                      { out = g_Eh;       ostride = 128; }
    load_W(sm, g_Wt_hi + l * DD * DD, g_Wt_lo + l * DD * DD);

    const uint32_t smb = smem_u32(sm);
    const float* bias = b + l * DD;
    const int lane = threadIdx.x & 31, w = threadIdx.x >> 5;
    const int m0 = (w & 1) * 32, n0 = (w >> 1) * 32;
    const int tig = lane & 3, gg = lane >> 2;

    float2 pf[16];
    long tile = blockIdx.x;
    if (tile < NODE_TILES) prefetch_tile<false>(h, tile, NN, pf);
    for (; tile < NODE_TILES; tile += gridDim.x) {
        commit_tile(sm, pf);
        __syncthreads();
        long nt = tile + gridDim.x;
        if (nt < NODE_TILES) prefetch_tile<false>(h, nt, NN, pf);

        float c[2][4][4];
        mma_compute(smb, c);

#pragma unroll
        for (int m = 0; m < 2; m++) {
            long r0 = tile * MT + m0 + m * 16 + gg;
#pragma unroll
            for (int n = 0; n < 4; n++) {
                int col = n0 + n * 8 + tig * 2;
                float2 bv = *(const float2*)(bias + col);
                if (r0 < NN)
                    *(float2*)(out + r0 * ostride + col) =
                        make_float2(c[m][n][0] + bv.x, c[m][n][1] + bv.y);
                if (r0 + 8 < NN)
                    *(float2*)(out + (r0 + 8) * ostride + col) =
                        make_float2(c[m][n][2] + bv.x, c[m][n][3] + bv.y);
            }
        }
        __syncthreads();   // all ldsm done before next commit overwrites A
    }
}

// ---------------- edge GEMM: persistent tiles + fused epilogue ---------------
__global__ void __launch_bounds__(256, 2) edge_gemm(const float* __restrict__ e,
        const float* __restrict__ b2, const int* __restrict__ src,
        const int* __restrict__ dst, const float* __restrict__ snorm_e,
        float* __restrict__ eout) {
    extern __shared__ __align__(16) char sm[];
    load_W(sm, g_Wt_hi + 2 * DD * DD, g_Wt_lo + 2 * DD * DD);

    const uint32_t smb = smem_u32(sm);
    float* sD = (float*)sm;   // 64 rows x 132 floats (reuses A region)
    const int lane = threadIdx.x & 31, w = threadIdx.x >> 5;
    const int m0 = (w & 1) * 32, n0 = (w >> 1) * 32;
    const int tig = lane & 3, gg = lane >> 2;
    const float se = snorm_e[0];
    const float4 bb = ((const float4*)b2)[lane];
    const float4* DB = (const float4*)g_DB;

    int gcur = -1;
    float4 s4 = make_float4(0, 0, 0, 0), q4 = make_float4(0, 0, 0, 0);

    float2 pf[16];
    long tile = blockIdx.x;
    if (tile < EDGE_TILES) prefetch_tile<true>(e, tile, EE, pf);
    for (; tile < EDGE_TILES; tile += gridDim.x) {
        commit_tile(sm, pf);
        __syncthreads();
        long nt = tile + gridDim.x;
        if (nt < EDGE_TILES) prefetch_tile<true>(e, nt, EE, pf);

        float c[2][4][4];
        mma_compute(smb, c);
        __syncthreads();   // before sD overwrites the A region

#pragma unroll
        for (int m = 0; m < 2; m++) {
            int r = m0 + m * 16 + gg;
#pragma unroll
            for (int n = 0; n < 4; n++) {
                int col = n0 + n * 8 + tig * 2;
                *(float2*)(sD + r * 132 + col) = make_float2(c[m][n][0], c[m][n][1]);
                *(float2*)(sD + (r + 8) * 132 + col) = make_float2(c[m][n][2], c[m][n][3]);
            }
        }
        __syncthreads();

        const long rbase = tile * MT + w * 8;
        const int4 sA = *(const int4*)(src + rbase);
        const int4 sB = *(const int4*)(src + rbase + 4);
        const int4 dA = *(const int4*)(dst + rbase);
        const int4 dB4 = *(const int4*)(dst + rbase + 4);
        const int svr[8] = {sA.x, sA.y, sA.z, sA.w, sB.x, sB.y, sB.z, sB.w};
        const int dvr[8] = {dA.x, dA.y, dA.z, dA.w, dB4.x, dB4.y, dB4.z, dB4.w};

#pragma unroll
        for (int r = 0; r < 8; r++) {
            const int row = w * 8 + r;
            const long grow = rbase + r;
            const int s = svr[r];
            const int d = dvr[r];
            float4 dv = *(float4*)(sD + row * 132 + lane * 4);
            float4 dh = DB[(size_t)s * 64 + lane];
            float4 bh = DB[(size_t)s * 64 + 32 + lane];
            float4 eh = ((const float4*)g_Eh)[(size_t)d * 32 + lane];
            float ex = dv.x + bb.x + dh.x + eh.x;
            float ey = dv.y + bb.y + dh.y + eh.y;
            float ez = dv.z + bb.z + dh.z + eh.z;
            float ew = dv.w + bb.w + dh.w + eh.w;
            float4 eo = make_float4(ex * se, ey * se, ez * se, ew * se);
            __stcs(((float4*)eout) + (size_t)grow * 32 + lane, eo);
            float sx = sigt(ex);
            float sy = sigt(ey);
            float sz = sigt(ez);
            float sv = sigt(ew);
            redv4(&g_num[d * DD + lane * 4],
                  make_float4(sx * bh.x, sy * bh.y, sz * bh.z, sv * bh.w));
            redv4(&g_den[d * DD + lane * 4], make_float4(sx, sy, sz, sv));
            const int gid = (int)(grow / GNE);
            if (gid != gcur) {
                if (gcur >= 0) {
                    redv4(&g_sum[NG * DD + gcur * DD + lane * 4], s4);
                    redv4(&g_sq[NG * DD + gcur * DD + lane * 4], q4);
                }
                gcur = gid;
                s4 = make_float4(0, 0, 0, 0);
                q4 = make_float4(0, 0, 0, 0);
            }
            s4.x += eo.x; s4.y += eo.y; s4.z += eo.z; s4.w += eo.w;
            q4.x = fmaf(eo.x, eo.x, q4.x); q4.y = fmaf(eo.y, eo.y, q4.y);
            q4.z = fmaf(eo.z, eo.z, q4.z); q4.w = fmaf(eo.w, eo.w, q4.w);
        }
        __syncthreads();   // epilogue reads of sD done before next commit
    }
    if (gcur >= 0) {
        redv4(&g_sum[NG * DD + gcur * DD + lane * 4], s4);
        redv4(&g_sq[NG * DD + gcur * DD + lane * 4], q4);
    }
}

// ---------------- node epilogue (vectorized) ----------------------------------
__global__ void node_epi(const float* __restrict__ h, const float* __restrict__ snorm_n,
                         float* __restrict__ outh) {
    const float sn = snorm_n[0];
    const int tot4 = NN * 32;
    for (int i = blockIdx.x * blockDim.x + threadIdx.x; i < tot4;
         i += gridDim.x * blockDim.x) {
        float4 den = ((const float4*)g_den)[i];
        float4 num = ((const float4*)g_num)[i];
        float4 ah  = ((const float4*)g_Ah)[i];
        float4 hv  = ((const float4*)h)[i];
        float4 o;
        o.x = ((den.x > 0.f) ? (ah.x + num.x / (den.x + EPS_RED)) : hv.x) * sn;
        o.y = ((den.y > 0.f) ? (ah.y + num.y / (den.y + EPS_RED)) : hv.y) * sn;
        o.z = ((den.z > 0.f) ? (ah.z + num.z / (den.z + EPS_RED)) : hv.z) * sn;
        o.w = ((den.w > 0.f) ? (ah.w + num.w / (den.w + EPS_RED)) : hv.w) * sn;
        ((float4*)outh)[i] = o;
    }
}

// ---------------- per-graph per-feature stats for h ----------------------------
__global__ void stats_kernel(const float* __restrict__ x, int size, int statOff) {
    int g = blockIdx.y;
    int per = (size + gridDim.x - 1) / gridDim.x;
    int r0 = blockIdx.x * per;
    int r1 = min(size, r0 + per);
    int f = threadIdx.x;
    const float* base = x + (size_t)g * size * DD;
    float s = 0.f, q = 0.f;
    for (int r = r0; r < r1; r++) {
        float v = __ldcs(&base[(size_t)r * DD + f]);
        s += v;
        q = fmaf(v, v, q);
    }
    if (r0 < r1) {
        atomicAdd(&g_sum[statOff + g * DD + f], s);
        atomicAdd(&g_sq[statOff + g * DD + f], q);
    }
}

__global__ void meanstd_kernel() {
    int i = blockIdx.x * blockDim.x + threadIdx.x;
    if (i >= 2 * NG * DD) return;
    float n = (i < NG * DD) ? (float)GNH : (float)GNE;
    float s = g_sum[i], q = g_sq[i];
    float mean = s / n;
    float var = (q - s * mean) / (n - 1.f);
    var = fmaxf(var, 0.f);
    g_mean[i] = mean;
    g_rstd[i] = 1.f / (sqrtf(var) + EPS_NORM);
}

// ---------------- finalize (vectorized): graphnorm + relu + residual ----------
__global__ void finalize_kernel(float* __restrict__ io, const float* __restrict__ resid,
                                const float* __restrict__ gamma,
                                const float* __restrict__ beta, int size, int statOff) {
    int g = blockIdx.y;
    size_t base4 = (size_t)g * size * 32;
    int tot4 = size * 32;
    const float4* mean4 = (const float4*)(g_mean + statOff + g * DD);
    const float4* rstd4 = (const float4*)(g_rstd + statOff + g * DD);
    for (int i = blockIdx.x * blockDim.x + threadIdx.x; i < tot4;
         i += gridDim.x * blockDim.x) {
        int f4 = i & 31;
        float4 xv = __ldcs(((const float4*)io) + base4 + i);
        float4 rv = __ldcs(((const float4*)resid) + base4 + i);
        float4 ga = ((const float4*)gamma)[f4];
        float4 be = ((const float4*)beta)[f4];
        float4 mn = mean4[f4];
        float4 rs = rstd4[f4];
        float4 o;
        o.x = rv.x + fmaxf(fmaf(ga.x, (xv.x - mn.x) * rs.x, be.x), 0.f);
        o.y = rv.y + fmaxf(fmaf(ga.y, (xv.y - mn.y) * rs.y, be.y), 0.f);
        o.z = rv.z + fmaxf(fmaf(ga.z, (xv.z - mn.z) * rs.z, be.z), 0.f);
        o.w = rv.w + fmaxf(fmaf(ga.w, (xv.w - mn.w) * rs.w, be.w), 0.f);
        __stcs(((float4*)io) + base4 + i, o);
    }
}

// ---------------- launcher -------------------------------------------------------
extern "C" void kernel_launch(void* const* d_in, const int* in_sizes, int n_in,
                              void* d_out, int out_size) {
    const float* h   = (const float*)d_in[0];
    const float* e   = (const float*)d_in[1];
    const int*   src = (const int*)d_in[2];
    const int*   dst = (const int*)d_in[3];
    const float* snn = (const float*)d_in[4];
    const float* sne = (const float*)d_in[5];
    const float* W   = (const float*)d_in[6];
    const float* b   = (const float*)d_in[7];
    const float* gam_h = (const float*)d_in[8];
    const float* bet_h = (const float*)d_in[9];
    const float* gam_e = (const float*)d_in[10];
    const float* bet_e = (const float*)d_in[11];

    float* out_h = (float*)d_out;
    float* out_e = out_h + (size_t)NN * DD;

    cudaFuncSetAttribute((const void*)node_gemm,
                         cudaFuncAttributeMaxDynamicSharedMemorySize, SMEM_BYTES);
    cudaFuncSetAttribute((const void*)edge_gemm,
                         cudaFuncAttributeMaxDynamicSharedMemorySize, SMEM_BYTES);

    zero_kernel<<<1024, 256>>>();
    splitW_kernel<<<(5 * DD * DD + 255) / 256, 256>>>(W);

    node_gemm<<<dim3(74, 4), 256, SMEM_BYTES>>>(h, b);
    edge_gemm<<<296, 256, SMEM_BYTES>>>(e, b + 2 * DD, src, dst, sne, out_e);

    node_epi<<<2048, 256>>>(h, snn, out_h);

    stats_kernel<<<dim3(64, NG), 128>>>(out_h, GNH, 0);
    meanstd_kernel<<<10, 256>>>();

    finalize_kernel<<<dim3(160, NG), 256>>>(out_h, h, gam_h, bet_h, GNH, 0);
    finalize_kernel<<<dim3(1024, NG), 256>>>(out_e, e, gam_e, bet_e, GNE, NG * DD);
}